// round 4
// baseline (speedup 1.0000x reference)
#include <cuda_runtime.h>
#include <cuda_bf16.h>
#include <mma.h>
#include <math.h>

using namespace nvcuda;

// ---------------- problem constants ----------------
#define TOK   32768            // B*H*W
#define EDIM  384
#define D1    768
#define BSZ   8
#define NSP   64               // H = W = 64
#define RPEW  512

// ---------------- device scratch (allocation-free) ----------------
__device__ __align__(256) __nv_bfloat16 g_xnb[(size_t)TOK * EDIM];   // normed x, bf16
__device__ __align__(256) float         g_ut [(size_t)D1 * TOK];     // u transposed [c][tok]
__device__ __align__(256) __nv_bfloat16 g_vt [(size_t)D1 * TOK];     // v transposed [c][tok]
__device__ __align__(256) __nv_bfloat16 g_gt [(size_t)D1 * TOK];     // g = u*tno, [c][tok]
__device__ __align__(256) __nv_bfloat16 g_wub[EDIM * D1];
__device__ __align__(256) __nv_bfloat16 g_wvb[EDIM * D1];
__device__ __align__(256) __nv_bfloat16 g_wob[D1 * EDIM];
__device__ __align__(256) float         g_at1[D1 * 128];             // W-axis coeffs [c][lag]
__device__ __align__(256) float         g_at2[D1 * 128];             // H-axis coeffs [c][lag]
__device__ __align__(256) float         g_rA [2 * 128 * RPEW];       // rpe ping
__device__ __align__(256) float         g_rB [2 * 128 * RPEW];       // rpe pong

// ---------------- fp32 -> bf16 weight convert ----------------
__global__ void cvt_kernel(const float* __restrict__ wu, const float* __restrict__ wv,
                           const float* __restrict__ wo) {
    int i = blockIdx.x * 256 + threadIdx.x;      // 294912 elems each
    if (i < EDIM * D1) {
        g_wub[i] = __float2bfloat16(wu[i]);
        g_wvb[i] = __float2bfloat16(wv[i]);
        g_wob[i] = __float2bfloat16(wo[i]);
    }
}

// ---------------- SimpleRMSNorm (one warp / token) ----------------
__global__ void norm_kernel(const float* __restrict__ x) {
    int w    = (blockIdx.x * blockDim.x + threadIdx.x) >> 5;
    int lane = threadIdx.x & 31;
    if (w >= TOK) return;
    const float* xr = x + (size_t)w * EDIM;
    float v[12], s = 0.f;
#pragma unroll
    for (int i = 0; i < 12; i++) { v[i] = xr[lane + 32 * i]; s += v[i] * v[i]; }
#pragma unroll
    for (int o = 16; o; o >>= 1) s += __shfl_xor_sync(0xffffffffu, s, o);
    float r = rsqrtf(s / (float)EDIM + 1e-6f);
    __nv_bfloat16* o = g_xnb + (size_t)w * EDIM;
#pragma unroll
    for (int i = 0; i < 12; i++) o[lane + 32 * i] = __float2bfloat16(v[i] * r);
}

// ---------------- GEMM: u/v = silu(xn @ W + b), write transposed [c][tok] --------
// block tile 128(m=tok) x 128(n=ch), K=384, BK=64. 8 warps (4m x 2n), warp 32x64.
#define GA_LD 72
#define GB_LD 136
#define GS_LD 132
#define GEMM_SMEM 67584   // stage 128*132*4 aliases A/B

__global__ void gemm_uv_kernel(const float* __restrict__ bu, const float* __restrict__ bv) {
    extern __shared__ char smem[];
    __nv_bfloat16* As = (__nv_bfloat16*)smem;                         // 128 x 72
    __nv_bfloat16* Bs = (__nv_bfloat16*)(smem + 128 * GA_LD * 2);     // 64 x 136
    float*         St = (float*)smem;                                  // 128 x 132 (alias)

    int m0 = blockIdx.x * 128;
    int n0 = blockIdx.y * 128;
    int mode = blockIdx.z;                                             // 0:u 1:v
    const __nv_bfloat16* W = mode ? g_wvb : g_wub;
    const float* bias = mode ? bv : bu;

    int tid = threadIdx.x;
    int wid = tid >> 5;
    int wm = wid & 3, wn = wid >> 2;

    wmma::fragment<wmma::accumulator, 16, 16, 16, float> acc[2][4];
#pragma unroll
    for (int i = 0; i < 2; i++)
#pragma unroll
        for (int j = 0; j < 4; j++) wmma::fill_fragment(acc[i][j], 0.f);

    for (int k0 = 0; k0 < EDIM; k0 += 64) {
#pragma unroll
        for (int l = 0; l < 4; l++) {            // A: 128 rows x 8 chunks(16B)
            int a = tid + 256 * l;
            int row = a >> 3, ch = a & 7;
            *(uint4*)(As + row * GA_LD + ch * 8) =
                *(const uint4*)(g_xnb + (size_t)(m0 + row) * EDIM + k0 + ch * 8);
        }
#pragma unroll
        for (int l = 0; l < 4; l++) {            // B: 64 rows x 16 chunks
            int a = tid + 256 * l;
            int row = a >> 4, ch = a & 15;
            *(uint4*)(Bs + row * GB_LD + ch * 8) =
                *(const uint4*)(W + (size_t)(k0 + row) * D1 + n0 + ch * 8);
        }
        __syncthreads();
#pragma unroll
        for (int kk = 0; kk < 64; kk += 16) {
            wmma::fragment<wmma::matrix_a, 16, 16, 16, __nv_bfloat16, wmma::row_major> af[2];
            wmma::fragment<wmma::matrix_b, 16, 16, 16, __nv_bfloat16, wmma::row_major> bf[4];
#pragma unroll
            for (int i = 0; i < 2; i++)
                wmma::load_matrix_sync(af[i], As + (wm * 32 + 16 * i) * GA_LD + kk, GA_LD);
#pragma unroll
            for (int j = 0; j < 4; j++)
                wmma::load_matrix_sync(bf[j], Bs + kk * GB_LD + wn * 64 + 16 * j, GB_LD);
#pragma unroll
            for (int i = 0; i < 2; i++)
#pragma unroll
                for (int j = 0; j < 4; j++) wmma::mma_sync(acc[i][j], af[i], bf[j], acc[i][j]);
        }
        __syncthreads();
    }
#pragma unroll
    for (int i = 0; i < 2; i++)
#pragma unroll
        for (int j = 0; j < 4; j++)
            wmma::store_matrix_sync(St + (wm * 32 + 16 * i) * GS_LD + wn * 64 + 16 * j,
                                    acc[i][j], GS_LD, wmma::mem_row_major);
    __syncthreads();
    // silu + transposed write: [c][tok]
#pragma unroll 4
    for (int l = 0; l < 64; l++) {
        int a = tid + 256 * l;          // 0..16383
        int j = a >> 7;                 // channel within tile
        int i = a & 127;                // token within tile (contiguous across threads)
        float v = St[i * GS_LD + j] + bias[n0 + j];
        float sv = v / (1.f + __expf(-v));
        size_t off = (size_t)(n0 + j) * TOK + m0 + i;
        if (mode == 0) g_ut[off] = sv;
        else           g_vt[off] = __float2bfloat16(sv);
    }
}

// ---------------- RPE layer 0: X0 = relu(p(r)*pw + pb), both nets -------------
__global__ void rpe_l0(const float* __restrict__ pw1, const float* __restrict__ pb1,
                       const float* __restrict__ pw2, const float* __restrict__ pb2) {
    int idx = blockIdx.x * 256 + threadIdx.x;    // 2*128*512 = 131072
    int net = idx >> 16;
    int rj  = idx & 65535;
    int r = rj >> 9, j = rj & 511;
    float p = (r == 0 || r == 64) ? 0.f : (r < 64 ? (float)r : (float)(r - 128));
    const float* pw = net ? pw2 : pw1;
    const float* pb = net ? pb2 : pb1;
    float v = p * pw[j] + pb[j];
    g_rA[idx] = v > 0.f ? v : 0.f;
}

// ---------------- RPE hidden: Y = relu(srms(X)) @ lw[layer] + lb[layer] -------
// grid (8 colTiles of 64, 8 rowTiles of 16, 2 nets), 256 thr.
__global__ void rpe_hidden(const float* __restrict__ lw1, const float* __restrict__ lb1,
                           const float* __restrict__ lw2, const float* __restrict__ lb2,
                           int layer, int src) {
    __shared__ float s[16][RPEW];
    __shared__ float srm[16];
    int net = blockIdx.z;
    int r0  = blockIdx.y * 16;
    int c0  = blockIdx.x * 64;
    const float* W  = (net ? lw2 : lw1) + (size_t)layer * RPEW * RPEW;
    const float* Bb = (net ? lb2 : lb1) + layer * RPEW;
    const float* Xi = (src ? g_rB : g_rA) + (size_t)net * 128 * RPEW + (size_t)r0 * RPEW;
    float*       Xo = (src ? g_rA : g_rB) + (size_t)net * 128 * RPEW;
    int tid = threadIdx.x;
#pragma unroll
    for (int l = 0; l < 8; l++) {                 // 16x512 floats = 2048 float4
        int a = tid + 256 * l;
        int row = a >> 7, q = a & 127;
        ((float4*)&s[row][0])[q] = ((const float4*)(Xi + (size_t)row * RPEW))[q];
    }
    __syncthreads();
    {
        int row = tid >> 4, l16 = tid & 15;
        float ss = 0.f;
        for (int k = l16; k < RPEW; k += 16) { float v = s[row][k]; ss += v * v; }
#pragma unroll
        for (int o = 8; o; o >>= 1) ss += __shfl_xor_sync(0xffffffffu, ss, o);
        if (l16 == 0) srm[row] = rsqrtf(ss / (float)RPEW + 1e-6f);
    }
    __syncthreads();
#pragma unroll
    for (int l = 0; l < 8; l++) {                 // normalize + relu in place
        int a = tid + 256 * l;
        int row = a >> 7, q = a & 127;
        float m = srm[row];
        float4 v = ((float4*)&s[row][0])[q];
        v.x = fmaxf(v.x * m, 0.f); v.y = fmaxf(v.y * m, 0.f);
        v.z = fmaxf(v.z * m, 0.f); v.w = fmaxf(v.w * m, 0.f);
        ((float4*)&s[row][0])[q] = v;
    }
    __syncthreads();
    int c  = c0 + (tid & 63);
    int rg = tid >> 6;                            // 4 row-groups x 4 rows
    float a0 = 0.f, a1 = 0.f, a2 = 0.f, a3 = 0.f;
    for (int k = 0; k < RPEW; k++) {
        float w = W[(size_t)k * RPEW + c];
        a0 += s[rg * 4 + 0][k] * w;
        a1 += s[rg * 4 + 1][k] * w;
        a2 += s[rg * 4 + 2][k] * w;
        a3 += s[rg * 4 + 3][k] * w;
    }
    float bb = Bb[c];
    Xo[(size_t)(r0 + rg * 4 + 0) * RPEW + c] = a0 + bb;
    Xo[(size_t)(r0 + rg * 4 + 1) * RPEW + c] = a1 + bb;
    Xo[(size_t)(r0 + rg * 4 + 2) * RPEW + c] = a2 + bb;
    Xo[(size_t)(r0 + rg * 4 + 3) * RPEW + c] = a3 + bb;
}

// ---------------- RPE final: a_tab[c][r] = (relu(srms(X)) @ ow + ob)[r][c] ----
// grid (12 colTiles of 64, 8 rowTiles of 16, 2 nets). Reads g_rB.
__global__ void rpe_final(const float* __restrict__ ow1, const float* __restrict__ ob1,
                          const float* __restrict__ ow2, const float* __restrict__ ob2) {
    __shared__ float s[16][RPEW];
    __shared__ float srm[16];
    int net = blockIdx.z;
    int r0  = blockIdx.y * 16;
    int c0  = blockIdx.x * 64;
    const float* W  = net ? ow2 : ow1;
    const float* Bb = net ? ob2 : ob1;
    const float* Xi = g_rB + (size_t)net * 128 * RPEW + (size_t)r0 * RPEW;
    float*       at = net ? g_at2 : g_at1;
    int tid = threadIdx.x;
#pragma unroll
    for (int l = 0; l < 8; l++) {
        int a = tid + 256 * l;
        int row = a >> 7, q = a & 127;
        ((float4*)&s[row][0])[q] = ((const float4*)(Xi + (size_t)row * RPEW))[q];
    }
    __syncthreads();
    {
        int row = tid >> 4, l16 = tid & 15;
        float ss = 0.f;
        for (int k = l16; k < RPEW; k += 16) { float v = s[row][k]; ss += v * v; }
#pragma unroll
        for (int o = 8; o; o >>= 1) ss += __shfl_xor_sync(0xffffffffu, ss, o);
        if (l16 == 0) srm[row] = rsqrtf(ss / (float)RPEW + 1e-6f);
    }
    __syncthreads();
#pragma unroll
    for (int l = 0; l < 8; l++) {
        int a = tid + 256 * l;
        int row = a >> 7, q = a & 127;
        float m = srm[row];
        float4 v = ((float4*)&s[row][0])[q];
        v.x = fmaxf(v.x * m, 0.f); v.y = fmaxf(v.y * m, 0.f);
        v.z = fmaxf(v.z * m, 0.f); v.w = fmaxf(v.w * m, 0.f);
        ((float4*)&s[row][0])[q] = v;
    }
    __syncthreads();
    int c  = c0 + (tid & 63);
    int rg = tid >> 6;
    float a0 = 0.f, a1 = 0.f, a2 = 0.f, a3 = 0.f;
    for (int k = 0; k < RPEW; k++) {
        float w = W[(size_t)k * D1 + c];
        a0 += s[rg * 4 + 0][k] * w;
        a1 += s[rg * 4 + 1][k] * w;
        a2 += s[rg * 4 + 2][k] * w;
        a3 += s[rg * 4 + 3][k] * w;
    }
    float bb = Bb[c];
    at[(size_t)c * 128 + r0 + rg * 4 + 0] = a0 + bb;
    at[(size_t)c * 128 + r0 + rg * 4 + 1] = a1 + bb;
    at[(size_t)c * 128 + r0 + rg * 4 + 2] = a2 + bb;
    at[(size_t)c * 128 + r0 + rg * 4 + 3] = a3 + bb;
}

// ---------------- TNO conv as per-(channel,batch) 64^3 GEMMs ------------------
// Out_cb = T2_c @ V_cb + V_cb @ T1t_c ; grid (192 cgroups of 4, 8 batches), 256 thr.
// smem: V(4x64x80 bf16)=40960 | T2 40960 | T1 40960 | stage(4x64x72 f32, alias T) | coef 4KB
#define CV_LD  80
#define CV_CH  5120            // 64*80 elems per channel tile
#define CVS_LD 72
#define CVS_CH 4608            // 64*72 floats
#define CONV_SMEM 126976

__global__ void conv_kernel() {
    extern __shared__ char sm[];
    __nv_bfloat16* V  = (__nv_bfloat16*)(sm);
    __nv_bfloat16* T2 = (__nv_bfloat16*)(sm + 40960);
    __nv_bfloat16* T1 = (__nv_bfloat16*)(sm + 81920);
    float*         St = (float*)(sm + 40960);           // alias over T2/T1
    float*         A1 = (float*)(sm + 122880);          // [4][128]
    float*         A2 = A1 + 512;

    int c0 = blockIdx.x * 4;
    int b  = blockIdx.y;
    int tid = threadIdx.x;

#pragma unroll
    for (int l = 0; l < 2; l++) {                       // coefficient tables
        int a = tid + 256 * l;                          // 0..511
        A1[a] = g_at1[(size_t)(c0 + (a >> 7)) * 128 + (a & 127)];
        A2[a] = g_at2[(size_t)(c0 + (a >> 7)) * 128 + (a & 127)];
    }
#pragma unroll
    for (int l = 0; l < 8; l++) {                       // V tiles: 4 ch x 512 uint4
        int a = tid + 256 * l;
        int cc = a >> 9, hw8 = a & 511;
        int h = hw8 >> 3, wq = hw8 & 7;
        *(uint4*)(V + cc * CV_CH + h * CV_LD + wq * 8) =
            *(const uint4*)(g_vt + (size_t)(c0 + cc) * TOK + b * 4096 + h * 64 + wq * 8);
    }
    __syncthreads();
#pragma unroll
    for (int l = 0; l < 64; l++) {                      // build Toeplitz matrices
        int a = tid + 256 * l;                          // 0..16383
        int cc = a >> 12, rs = a & 4095;
        int r = rs >> 6, s = rs & 63;
        T2[cc * CV_CH + r * CV_LD + s] = __float2bfloat16(A2[cc * 128 + ((r - s) & 127)]);
        T1[cc * CV_CH + r * CV_LD + s] = __float2bfloat16(A1[cc * 128 + ((s - r) & 127)]);
    }
    __syncthreads();

    int wid = tid >> 5;
    int cc  = wid >> 1;
    int r0  = (wid & 1) * 32;
    __nv_bfloat16* Vc  = V  + cc * CV_CH;
    __nv_bfloat16* T2c = T2 + cc * CV_CH;
    __nv_bfloat16* T1c = T1 + cc * CV_CH;

    wmma::fragment<wmma::accumulator, 16, 16, 16, float> acc[2][4];
#pragma unroll
    for (int i = 0; i < 2; i++)
#pragma unroll
        for (int j = 0; j < 4; j++) wmma::fill_fragment(acc[i][j], 0.f);

#pragma unroll
    for (int kt = 0; kt < 4; kt++) {
        wmma::fragment<wmma::matrix_a, 16, 16, 16, __nv_bfloat16, wmma::row_major> af[2];
        wmma::fragment<wmma::matrix_b, 16, 16, 16, __nv_bfloat16, wmma::row_major> bf[4];
        // product 1: T2 @ V
#pragma unroll
        for (int i = 0; i < 2; i++)
            wmma::load_matrix_sync(af[i], T2c + (r0 + 16 * i) * CV_LD + kt * 16, CV_LD);
#pragma unroll
        for (int j = 0; j < 4; j++)
            wmma::load_matrix_sync(bf[j], Vc + kt * 16 * CV_LD + 16 * j, CV_LD);
#pragma unroll
        for (int i = 0; i < 2; i++)
#pragma unroll
            for (int j = 0; j < 4; j++) wmma::mma_sync(acc[i][j], af[i], bf[j], acc[i][j]);
        // product 2: V @ T1t
#pragma unroll
        for (int i = 0; i < 2; i++)
            wmma::load_matrix_sync(af[i], Vc + (r0 + 16 * i) * CV_LD + kt * 16, CV_LD);
#pragma unroll
        for (int j = 0; j < 4; j++)
            wmma::load_matrix_sync(bf[j], T1c + kt * 16 * CV_LD + 16 * j, CV_LD);
#pragma unroll
        for (int i = 0; i < 2; i++)
#pragma unroll
            for (int j = 0; j < 4; j++) wmma::mma_sync(acc[i][j], af[i], bf[j], acc[i][j]);
    }
    __syncthreads();                                    // before aliasing T with stage
#pragma unroll
    for (int i = 0; i < 2; i++)
#pragma unroll
        for (int j = 0; j < 4; j++)
            wmma::store_matrix_sync(St + cc * CVS_CH + (r0 + 16 * i) * CVS_LD + 16 * j,
                                    acc[i][j], CVS_LD, wmma::mem_row_major);
    __syncthreads();
#pragma unroll 4
    for (int l = 0; l < 64; l++) {                      // g = u * tno -> bf16
        int a = tid + 256 * l;                          // 0..16383
        int cc2 = a >> 12, hw = a & 4095;
        int h = hw >> 6, w = hw & 63;
        float t = St[cc2 * CVS_CH + h * CVS_LD + w];
        float u = g_ut[(size_t)(c0 + cc2) * TOK + b * 4096 + hw];
        g_gt[(size_t)(c0 + cc2) * TOK + b * 4096 + hw] = __float2bfloat16(t * u);
    }
}

// ---------------- final GEMM: out = g @ Wo + bo + x ---------------------------
// A = g_t col-major (M=TOK, K=768), B = Wo row-major (768x384). Tile 128x128, BK=64.
#define GO_LD 136
__global__ void gemm_out_kernel(const float* __restrict__ x, const float* __restrict__ bo,
                                float* __restrict__ out) {
    extern __shared__ char smem[];
    __nv_bfloat16* As = (__nv_bfloat16*)smem;                     // [k=64][m=128] ld 136
    __nv_bfloat16* Bs = (__nv_bfloat16*)(smem + 64 * GO_LD * 2);  // [k=64][n=128] ld 136
    float*         St = (float*)smem;                              // 128x132 alias

    int m0 = blockIdx.x * 128;
    int n0 = blockIdx.y * 128;
    int tid = threadIdx.x;
    int wid = tid >> 5;
    int wm = wid & 3, wn = wid >> 2;

    wmma::fragment<wmma::accumulator, 16, 16, 16, float> acc[2][4];
#pragma unroll
    for (int i = 0; i < 2; i++)
#pragma unroll
        for (int j = 0; j < 4; j++) wmma::fill_fragment(acc[i][j], 0.f);

    for (int k0 = 0; k0 < D1; k0 += 64) {
#pragma unroll
        for (int l = 0; l < 4; l++) {            // A: 64 k-rows x 16 chunks of m
            int a = tid + 256 * l;
            int row = a >> 4, ch = a & 15;
            *(uint4*)(As + row * GO_LD + ch * 8) =
                *(const uint4*)(g_gt + (size_t)(k0 + row) * TOK + m0 + ch * 8);
        }
#pragma unroll
        for (int l = 0; l < 4; l++) {            // B: 64 k-rows x 16 chunks of n
            int a = tid + 256 * l;
            int row = a >> 4, ch = a & 15;
            *(uint4*)(Bs + row * GO_LD + ch * 8) =
                *(const uint4*)(g_wob + (size_t)(k0 + row) * EDIM + n0 + ch * 8);
        }
        __syncthreads();
#pragma unroll
        for (int kk = 0; kk < 64; kk += 16) {
            wmma::fragment<wmma::matrix_a, 16, 16, 16, __nv_bfloat16, wmma::col_major> af[2];
            wmma::fragment<wmma::matrix_b, 16, 16, 16, __nv_bfloat16, wmma::row_major> bf[4];
#pragma unroll
            for (int i = 0; i < 2; i++)
                wmma::load_matrix_sync(af[i], As + kk * GO_LD + wm * 32 + 16 * i, GO_LD);
#pragma unroll
            for (int j = 0; j < 4; j++)
                wmma::load_matrix_sync(bf[j], Bs + kk * GO_LD + wn * 64 + 16 * j, GO_LD);
#pragma unroll
            for (int i = 0; i < 2; i++)
#pragma unroll
                for (int j = 0; j < 4; j++) wmma::mma_sync(acc[i][j], af[i], bf[j], acc[i][j]);
        }
        __syncthreads();
    }
#pragma unroll
    for (int i = 0; i < 2; i++)
#pragma unroll
        for (int j = 0; j < 4; j++)
            wmma::store_matrix_sync(St + (wm * 32 + 16 * i) * GS_LD + wn * 64 + 16 * j,
                                    acc[i][j], GS_LD, wmma::mem_row_major);
    __syncthreads();
#pragma unroll 4
    for (int l = 0; l < 64; l++) {
        int a = tid + 256 * l;
        int i = a >> 7, j = a & 127;             // j contiguous -> coalesced out/x
        size_t go = (size_t)(m0 + i) * EDIM + n0 + j;
        out[go] = St[i * GS_LD + j] + bo[n0 + j] + x[go];
    }
}

// ---------------- launch ------------------------------------------------------
extern "C" void kernel_launch(void* const* d_in, const int* in_sizes, int n_in,
                              void* d_out, int out_size) {
    (void)in_sizes; (void)n_in; (void)out_size;
    const float* x     = (const float*)d_in[0];
    const float* Wu    = (const float*)d_in[3];
    const float* bu    = (const float*)d_in[4];
    const float* Wv    = (const float*)d_in[5];
    const float* bv    = (const float*)d_in[6];
    const float* Wo    = (const float*)d_in[7];
    const float* bo    = (const float*)d_in[8];
    const float* r1_pw = (const float*)d_in[9];
    const float* r1_pb = (const float*)d_in[10];
    const float* r1_lw = (const float*)d_in[11];
    const float* r1_lb = (const float*)d_in[12];
    const float* r1_ow = (const float*)d_in[13];
    const float* r1_ob = (const float*)d_in[14];
    const float* r2_pw = (const float*)d_in[15];
    const float* r2_pb = (const float*)d_in[16];
    const float* r2_lw = (const float*)d_in[17];
    const float* r2_lb = (const float*)d_in[18];
    const float* r2_ow = (const float*)d_in[19];
    const float* r2_ob = (const float*)d_in[20];
    float* out = (float*)d_out;

    cudaFuncSetAttribute(gemm_uv_kernel,  cudaFuncAttributeMaxDynamicSharedMemorySize, GEMM_SMEM);
    cudaFuncSetAttribute(gemm_out_kernel, cudaFuncAttributeMaxDynamicSharedMemorySize, GEMM_SMEM);
    cudaFuncSetAttribute(conv_kernel,     cudaFuncAttributeMaxDynamicSharedMemorySize, CONV_SMEM);

    cvt_kernel <<<1152, 256>>>(Wu, Wv, Wo);
    norm_kernel<<<4096, 256>>>(x);
    gemm_uv_kernel<<<dim3(TOK / 128, D1 / 128, 2), 256, GEMM_SMEM>>>(bu, bv);

    rpe_l0<<<512, 256>>>(r1_pw, r1_pb, r2_pw, r2_pb);                       // -> g_rA
    rpe_hidden<<<dim3(8, 8, 2), 256>>>(r1_lw, r1_lb, r2_lw, r2_lb, 0, 0);   // rA -> rB
    rpe_hidden<<<dim3(8, 8, 2), 256>>>(r1_lw, r1_lb, r2_lw, r2_lb, 1, 1);   // rB -> rA
    rpe_hidden<<<dim3(8, 8, 2), 256>>>(r1_lw, r1_lb, r2_lw, r2_lb, 2, 0);   // rA -> rB
    rpe_final <<<dim3(12, 8, 2), 256>>>(r1_ow, r1_ob, r2_ow, r2_ob);        // rB -> a_tabs

    conv_kernel<<<dim3(D1 / 4, BSZ), 256, CONV_SMEM>>>();
    gemm_out_kernel<<<dim3(TOK / 128, EDIM / 128), 256, GEMM_SMEM>>>(x, bo, out);
}

// round 6
// speedup vs baseline: 1.5777x; 1.5777x over previous
#include <cuda_runtime.h>
#include <cuda_bf16.h>
#include <mma.h>
#include <math.h>
#include <stdint.h>

using namespace nvcuda;

// ---------------- problem constants ----------------
#define TOK   32768            // B*H*W
#define EDIM  384
#define D1    768
#define BSZ   8
#define NSP   64               // H = W = 64
#define RPEW  512

// ---------------- device scratch (allocation-free) ----------------
__device__ __align__(256) __nv_bfloat16 g_xnb[(size_t)TOK * EDIM];   // normed x, bf16
__device__ __align__(256) float         g_ut [(size_t)D1 * TOK];     // u transposed [c][tok]
__device__ __align__(256) __nv_bfloat16 g_vt [(size_t)D1 * TOK];     // v transposed [c][tok]
__device__ __align__(256) __nv_bfloat16 g_gt [(size_t)D1 * TOK];     // g = u*tno, [c][tok]
__device__ __align__(256) __nv_bfloat16 g_wub[EDIM * D1];
__device__ __align__(256) __nv_bfloat16 g_wvb[EDIM * D1];
__device__ __align__(256) __nv_bfloat16 g_wob[D1 * EDIM];
__device__ __align__(256) float         g_at1[D1 * 128];             // W-axis coeffs [c][lag]
__device__ __align__(256) float         g_at2[D1 * 128];             // H-axis coeffs [c][lag]
__device__ __align__(256) float         g_rA [2 * 128 * RPEW];       // rpe ping
__device__ __align__(256) float         g_rB [2 * 128 * RPEW];       // rpe pong
__device__ __align__(256) __nv_bfloat16 g_T2b [(size_t)D1 * 64 * 64]; // T2[c][i][k]
__device__ __align__(256) __nv_bfloat16 g_T1tb[(size_t)D1 * 64 * 64]; // T1t[c][k][j]

// ---------------- cp.async helpers ----------------
__device__ __forceinline__ void cpa16(void* dst, const void* src) {
    unsigned int s = (unsigned int)__cvta_generic_to_shared(dst);
    asm volatile("cp.async.cg.shared.global [%0], [%1], 16;\n" :: "r"(s), "l"(src));
}
#define CP_COMMIT()  asm volatile("cp.async.commit_group;\n" ::: "memory")
#define CP_WAIT0()   asm volatile("cp.async.wait_group 0;\n" ::: "memory")
#define CP_WAIT1()   asm volatile("cp.async.wait_group 1;\n" ::: "memory")

// ---------------- fp32 -> bf16 weight convert ----------------
__global__ void cvt_kernel(const float* __restrict__ wu, const float* __restrict__ wv,
                           const float* __restrict__ wo) {
    int i = blockIdx.x * 256 + threadIdx.x;      // 294912 elems each
    if (i < EDIM * D1) {
        g_wub[i] = __float2bfloat16(wu[i]);
        g_wvb[i] = __float2bfloat16(wv[i]);
        g_wob[i] = __float2bfloat16(wo[i]);
    }
}

// ---------------- SimpleRMSNorm (one warp / token) ----------------
__global__ void norm_kernel(const float* __restrict__ x) {
    int w    = (blockIdx.x * blockDim.x + threadIdx.x) >> 5;
    int lane = threadIdx.x & 31;
    if (w >= TOK) return;
    const float* xr = x + (size_t)w * EDIM;
    float v[12], s = 0.f;
#pragma unroll
    for (int i = 0; i < 12; i++) { v[i] = xr[lane + 32 * i]; s += v[i] * v[i]; }
#pragma unroll
    for (int o = 16; o; o >>= 1) s += __shfl_xor_sync(0xffffffffu, s, o);
    float r = rsqrtf(s / (float)EDIM + 1e-6f);
    __nv_bfloat16* o = g_xnb + (size_t)w * EDIM;
#pragma unroll
    for (int i = 0; i < 12; i++) o[lane + 32 * i] = __float2bfloat16(v[i] * r);
}

// ---------------- GEMM: u/v = silu(xn @ W + b), transposed output, 2-stage pipe
#define GA_LD 72
#define GB_LD 136
#define GS_LD 132
#define A_STG (128 * GA_LD)          // elems per A stage
#define B_STG (64 * GB_LD)
#define GEMM_SMEM ((2 * A_STG + 2 * B_STG) * 2)   // 71680 B; St (67584) aliases

__global__ void gemm_uv_kernel(const float* __restrict__ bu, const float* __restrict__ bv) {
    extern __shared__ char smem[];
    __nv_bfloat16* As = (__nv_bfloat16*)smem;                         // 2 x 128x72
    __nv_bfloat16* Bs = (__nv_bfloat16*)(smem + 2 * A_STG * 2);       // 2 x 64x136
    float*         St = (float*)smem;                                  // 128x132 alias

    int m0 = blockIdx.x * 128;
    int n0 = blockIdx.y * 128;
    int mode = blockIdx.z;                                             // 0:u 1:v
    const __nv_bfloat16* W = mode ? g_wvb : g_wub;
    const float* bias = mode ? bv : bu;

    int tid = threadIdx.x;
    int wid = tid >> 5;
    int wm = wid & 3, wn = wid >> 2;

    wmma::fragment<wmma::accumulator, 16, 16, 16, float> acc[2][4];
#pragma unroll
    for (int i = 0; i < 2; i++)
#pragma unroll
        for (int j = 0; j < 4; j++) wmma::fill_fragment(acc[i][j], 0.f);

#define UV_LOAD(k0, st)                                                              \
    {                                                                                \
        _Pragma("unroll")                                                            \
        for (int l = 0; l < 4; l++) {            /* A: 128 rows x 8 chunks */        \
            int a = tid + 256 * l;                                                   \
            int row = a >> 3, ch = a & 7;                                            \
            cpa16(As + (st) * A_STG + row * GA_LD + ch * 8,                          \
                  g_xnb + (size_t)(m0 + row) * EDIM + (k0) + ch * 8);                \
        }                                                                            \
        _Pragma("unroll")                                                            \
        for (int l = 0; l < 4; l++) {            /* B: 64 rows x 16 chunks */        \
            int a = tid + 256 * l;                                                   \
            int row = a >> 4, ch = a & 15;                                           \
            cpa16(Bs + (st) * B_STG + row * GB_LD + ch * 8,                          \
                  W + (size_t)((k0) + row) * D1 + n0 + ch * 8);                      \
        }                                                                            \
        CP_COMMIT();                                                                 \
    }

    UV_LOAD(0, 0);
    const int NT = EDIM / 64;                    // 6
    for (int t = 0; t < NT; t++) {
        if (t + 1 < NT) { UV_LOAD((t + 1) * 64, (t + 1) & 1); CP_WAIT1(); }
        else           { CP_WAIT0(); }
        __syncthreads();
        const __nv_bfloat16* Ac = As + (t & 1) * A_STG;
        const __nv_bfloat16* Bc = Bs + (t & 1) * B_STG;
#pragma unroll
        for (int kk = 0; kk < 64; kk += 16) {
            wmma::fragment<wmma::matrix_a, 16, 16, 16, __nv_bfloat16, wmma::row_major> af[2];
            wmma::fragment<wmma::matrix_b, 16, 16, 16, __nv_bfloat16, wmma::row_major> bf[4];
#pragma unroll
            for (int i = 0; i < 2; i++)
                wmma::load_matrix_sync(af[i], Ac + (wm * 32 + 16 * i) * GA_LD + kk, GA_LD);
#pragma unroll
            for (int j = 0; j < 4; j++)
                wmma::load_matrix_sync(bf[j], Bc + kk * GB_LD + wn * 64 + 16 * j, GB_LD);
#pragma unroll
            for (int i = 0; i < 2; i++)
#pragma unroll
                for (int j = 0; j < 4; j++) wmma::mma_sync(acc[i][j], af[i], bf[j], acc[i][j]);
        }
        __syncthreads();
    }
#pragma unroll
    for (int i = 0; i < 2; i++)
#pragma unroll
        for (int j = 0; j < 4; j++)
            wmma::store_matrix_sync(St + (wm * 32 + 16 * i) * GS_LD + wn * 64 + 16 * j,
                                    acc[i][j], GS_LD, wmma::mem_row_major);
    __syncthreads();
    // silu + transposed write: [c][tok]
#pragma unroll 4
    for (int l = 0; l < 64; l++) {
        int a = tid + 256 * l;          // 0..16383
        int j = a >> 7;                 // channel within tile
        int i = a & 127;                // token within tile (contiguous across threads)
        float v = St[i * GS_LD + j] + bias[n0 + j];
        float sv = v / (1.f + __expf(-v));
        size_t off = (size_t)(n0 + j) * TOK + m0 + i;
        if (mode == 0) g_ut[off] = sv;
        else           g_vt[off] = __float2bfloat16(sv);
    }
#undef UV_LOAD
}

// ---------------- RPE layer 0: X0 = relu(p(r)*pw + pb), both nets -------------
__global__ void rpe_l0(const float* __restrict__ pw1, const float* __restrict__ pb1,
                       const float* __restrict__ pw2, const float* __restrict__ pb2) {
    int idx = blockIdx.x * 256 + threadIdx.x;    // 2*128*512 = 131072
    int net = idx >> 16;
    int rj  = idx & 65535;
    int r = rj >> 9, j = rj & 511;
    float p = (r == 0 || r == 64) ? 0.f : (r < 64 ? (float)r : (float)(r - 128));
    const float* pw = net ? pw2 : pw1;
    const float* pb = net ? pb2 : pb1;
    float v = p * pw[j] + pb[j];
    g_rA[idx] = v > 0.f ? v : 0.f;
}

// ---------------- RPE hidden: Y = relu(srms(X)) @ lw[layer] + lb[layer] -------
__global__ void rpe_hidden(const float* __restrict__ lw1, const float* __restrict__ lb1,
                           const float* __restrict__ lw2, const float* __restrict__ lb2,
                           int layer, int src) {
    __shared__ float s[16][RPEW];
    __shared__ float srm[16];
    int net = blockIdx.z;
    int r0  = blockIdx.y * 16;
    int c0  = blockIdx.x * 64;
    const float* W  = (net ? lw2 : lw1) + (size_t)layer * RPEW * RPEW;
    const float* Bb = (net ? lb2 : lb1) + layer * RPEW;
    const float* Xi = (src ? g_rB : g_rA) + (size_t)net * 128 * RPEW + (size_t)r0 * RPEW;
    float*       Xo = (src ? g_rA : g_rB) + (size_t)net * 128 * RPEW;
    int tid = threadIdx.x;
#pragma unroll
    for (int l = 0; l < 8; l++) {
        int a = tid + 256 * l;
        int row = a >> 7, q = a & 127;
        ((float4*)&s[row][0])[q] = ((const float4*)(Xi + (size_t)row * RPEW))[q];
    }
    __syncthreads();
    {
        int row = tid >> 4, l16 = tid & 15;
        float ss = 0.f;
        for (int k = l16; k < RPEW; k += 16) { float v = s[row][k]; ss += v * v; }
#pragma unroll
        for (int o = 8; o; o >>= 1) ss += __shfl_xor_sync(0xffffffffu, ss, o);
        if (l16 == 0) srm[row] = rsqrtf(ss / (float)RPEW + 1e-6f);
    }
    __syncthreads();
#pragma unroll
    for (int l = 0; l < 8; l++) {
        int a = tid + 256 * l;
        int row = a >> 7, q = a & 127;
        float m = srm[row];
        float4 v = ((float4*)&s[row][0])[q];
        v.x = fmaxf(v.x * m, 0.f); v.y = fmaxf(v.y * m, 0.f);
        v.z = fmaxf(v.z * m, 0.f); v.w = fmaxf(v.w * m, 0.f);
        ((float4*)&s[row][0])[q] = v;
    }
    __syncthreads();
    int c  = c0 + (tid & 63);
    int rg = tid >> 6;
    float a0 = 0.f, a1 = 0.f, a2 = 0.f, a3 = 0.f;
    for (int k = 0; k < RPEW; k++) {
        float w = W[(size_t)k * RPEW + c];
        a0 += s[rg * 4 + 0][k] * w;
        a1 += s[rg * 4 + 1][k] * w;
        a2 += s[rg * 4 + 2][k] * w;
        a3 += s[rg * 4 + 3][k] * w;
    }
    float bb = Bb[c];
    Xo[(size_t)(r0 + rg * 4 + 0) * RPEW + c] = a0 + bb;
    Xo[(size_t)(r0 + rg * 4 + 1) * RPEW + c] = a1 + bb;
    Xo[(size_t)(r0 + rg * 4 + 2) * RPEW + c] = a2 + bb;
    Xo[(size_t)(r0 + rg * 4 + 3) * RPEW + c] = a3 + bb;
}

// ---------------- RPE final: a_tab[c][r] ----
__global__ void rpe_final(const float* __restrict__ ow1, const float* __restrict__ ob1,
                          const float* __restrict__ ow2, const float* __restrict__ ob2) {
    __shared__ float s[16][RPEW];
    __shared__ float srm[16];
    int net = blockIdx.z;
    int r0  = blockIdx.y * 16;
    int c0  = blockIdx.x * 64;
    const float* W  = net ? ow2 : ow1;
    const float* Bb = net ? ob2 : ob1;
    const float* Xi = g_rB + (size_t)net * 128 * RPEW + (size_t)r0 * RPEW;
    float*       at = net ? g_at2 : g_at1;
    int tid = threadIdx.x;
#pragma unroll
    for (int l = 0; l < 8; l++) {
        int a = tid + 256 * l;
        int row = a >> 7, q = a & 127;
        ((float4*)&s[row][0])[q] = ((const float4*)(Xi + (size_t)row * RPEW))[q];
    }
    __syncthreads();
    {
        int row = tid >> 4, l16 = tid & 15;
        float ss = 0.f;
        for (int k = l16; k < RPEW; k += 16) { float v = s[row][k]; ss += v * v; }
#pragma unroll
        for (int o = 8; o; o >>= 1) ss += __shfl_xor_sync(0xffffffffu, ss, o);
        if (l16 == 0) srm[row] = rsqrtf(ss / (float)RPEW + 1e-6f);
    }
    __syncthreads();
#pragma unroll
    for (int l = 0; l < 8; l++) {
        int a = tid + 256 * l;
        int row = a >> 7, q = a & 127;
        float m = srm[row];
        float4 v = ((float4*)&s[row][0])[q];
        v.x = fmaxf(v.x * m, 0.f); v.y = fmaxf(v.y * m, 0.f);
        v.z = fmaxf(v.z * m, 0.f); v.w = fmaxf(v.w * m, 0.f);
        ((float4*)&s[row][0])[q] = v;
    }
    __syncthreads();
    int c  = c0 + (tid & 63);
    int rg = tid >> 6;
    float a0 = 0.f, a1 = 0.f, a2 = 0.f, a3 = 0.f;
    for (int k = 0; k < RPEW; k++) {
        float w = W[(size_t)k * D1 + c];
        a0 += s[rg * 4 + 0][k] * w;
        a1 += s[rg * 4 + 1][k] * w;
        a2 += s[rg * 4 + 2][k] * w;
        a3 += s[rg * 4 + 3][k] * w;
    }
    float bb = Bb[c];
    at[(size_t)c * 128 + r0 + rg * 4 + 0] = a0 + bb;
    at[(size_t)c * 128 + r0 + rg * 4 + 1] = a1 + bb;
    at[(size_t)c * 128 + r0 + rg * 4 + 2] = a2 + bb;
    at[(size_t)c * 128 + r0 + rg * 4 + 3] = a3 + bb;
}

// ---------------- Toeplitz table build: one channel per block ----------------
__global__ void toep_kernel() {
    __shared__ float a1[128], a2[128];
    int c = blockIdx.x;
    int tid = threadIdx.x;
    if (tid < 128) {
        a1[tid] = g_at1[(size_t)c * 128 + tid];
        a2[tid] = g_at2[(size_t)c * 128 + tid];
    }
    __syncthreads();
#pragma unroll
    for (int l = 0; l < 16; l++) {
        int idx = tid + 256 * l;                 // 0..4095
        int r = idx >> 6, s = idx & 63;
        g_T2b [(size_t)c * 4096 + idx] = __float2bfloat16(a2[(r - s) & 127]);  // T2[i][k]
        g_T1tb[(size_t)c * 4096 + idx] = __float2bfloat16(a1[(s - r) & 127]);  // T1t[k][j]
    }
}

// ---------------- TNO conv: 2 channels x 1 batch per block, cp.async loads ----
#define CT_LD 72
#define CT_CH 4608            // 64*72 elems per channel tile
#define CONV_SMEM 55296       // T2(18432) + T1t(18432) + V(18432); St aliases T2+T1t

__global__ void conv_kernel() {
    extern __shared__ char sm[];
    __nv_bfloat16* T2s = (__nv_bfloat16*)(sm);
    __nv_bfloat16* T1s = (__nv_bfloat16*)(sm + 18432);
    __nv_bfloat16* Vs  = (__nv_bfloat16*)(sm + 36864);
    float*         St  = (float*)sm;                    // 2*64*72*4 = 36864 alias

    int c0 = blockIdx.x * 2;
    int b  = blockIdx.y;
    int tid = threadIdx.x;

#pragma unroll
    for (int l = 0; l < 4; l++) {                       // 1024 uint4 each tensor
        int a = tid + 256 * l;
        int cc = a >> 9, rq = a & 511;
        int r = rq >> 3, q = rq & 7;
        cpa16(T2s + cc * CT_CH + r * CT_LD + q * 8,
              g_T2b + (size_t)(c0 + cc) * 4096 + r * 64 + q * 8);
        cpa16(T1s + cc * CT_CH + r * CT_LD + q * 8,
              g_T1tb + (size_t)(c0 + cc) * 4096 + r * 64 + q * 8);
        cpa16(Vs + cc * CT_CH + r * CT_LD + q * 8,
              g_vt + (size_t)(c0 + cc) * TOK + b * 4096 + r * 64 + q * 8);
    }
    CP_COMMIT();
    CP_WAIT0();
    __syncthreads();

    int wid = tid >> 5;
    int cc  = wid >> 2;                                 // 2 channels, 4 warps each
    int r0  = (wid & 3) * 16;                           // 16 rows per warp
    __nv_bfloat16* Vc  = Vs  + cc * CT_CH;
    __nv_bfloat16* T2c = T2s + cc * CT_CH;
    __nv_bfloat16* T1c = T1s + cc * CT_CH;

    wmma::fragment<wmma::accumulator, 16, 16, 16, float> acc[4];
#pragma unroll
    for (int j = 0; j < 4; j++) wmma::fill_fragment(acc[j], 0.f);

#pragma unroll
    for (int kt = 0; kt < 4; kt++) {
        wmma::fragment<wmma::matrix_a, 16, 16, 16, __nv_bfloat16, wmma::row_major> af;
        wmma::fragment<wmma::matrix_b, 16, 16, 16, __nv_bfloat16, wmma::row_major> bf[4];
        // product 1: T2 @ V
        wmma::load_matrix_sync(af, T2c + r0 * CT_LD + kt * 16, CT_LD);
#pragma unroll
        for (int j = 0; j < 4; j++)
            wmma::load_matrix_sync(bf[j], Vc + kt * 16 * CT_LD + 16 * j, CT_LD);
#pragma unroll
        for (int j = 0; j < 4; j++) wmma::mma_sync(acc[j], af, bf[j], acc[j]);
        // product 2: V @ T1t
        wmma::load_matrix_sync(af, Vc + r0 * CT_LD + kt * 16, CT_LD);
#pragma unroll
        for (int j = 0; j < 4; j++)
            wmma::load_matrix_sync(bf[j], T1c + kt * 16 * CT_LD + 16 * j, CT_LD);
#pragma unroll
        for (int j = 0; j < 4; j++) wmma::mma_sync(acc[j], af, bf[j], acc[j]);
    }
    __syncthreads();                                    // before aliasing T with St
#pragma unroll
    for (int j = 0; j < 4; j++)
        wmma::store_matrix_sync(St + cc * CT_CH + r0 * CT_LD + 16 * j,
                                acc[j], CT_LD, wmma::mem_row_major);
    __syncthreads();
#pragma unroll 4
    for (int l = 0; l < 32; l++) {                      // g = u * tno -> bf16
        int a = tid + 256 * l;                          // 0..8191
        int cc2 = a >> 12, hw = a & 4095;
        int h = hw >> 6, w = hw & 63;
        float t = St[cc2 * CT_CH + h * CT_LD + w];
        float u = g_ut[(size_t)(c0 + cc2) * TOK + b * 4096 + hw];
        g_gt[(size_t)(c0 + cc2) * TOK + b * 4096 + hw] = __float2bfloat16(t * u);
    }
}

// ---------------- final GEMM: out = g @ Wo + bo + x, 2-stage pipeline ---------
#define GO_LD 136
#define O_STG (64 * GO_LD)
#define GOUT_SMEM ((4 * O_STG) * 2)   // 69632 B; St (67584) aliases

__global__ void gemm_out_kernel(const float* __restrict__ x, const float* __restrict__ bo,
                                float* __restrict__ out) {
    extern __shared__ char smem[];
    __nv_bfloat16* As = (__nv_bfloat16*)smem;                     // 2 x [64][136]
    __nv_bfloat16* Bs = (__nv_bfloat16*)(smem + 2 * O_STG * 2);   // 2 x [64][136]
    float*         St = (float*)smem;                              // 128x132 alias

    int m0 = blockIdx.x * 128;
    int n0 = blockIdx.y * 128;
    int tid = threadIdx.x;
    int wid = tid >> 5;
    int wm = wid & 3, wn = wid >> 2;

    wmma::fragment<wmma::accumulator, 16, 16, 16, float> acc[2][4];
#pragma unroll
    for (int i = 0; i < 2; i++)
#pragma unroll
        for (int j = 0; j < 4; j++) wmma::fill_fragment(acc[i][j], 0.f);

#define GO_LOAD(k0, st)                                                              \
    {                                                                                \
        _Pragma("unroll")                                                            \
        for (int l = 0; l < 4; l++) {            /* A: 64 k-rows x 16 m-chunks */    \
            int a = tid + 256 * l;                                                   \
            int row = a >> 4, ch = a & 15;                                           \
            cpa16(As + (st) * O_STG + row * GO_LD + ch * 8,                          \
                  g_gt + (size_t)((k0) + row) * TOK + m0 + ch * 8);                  \
        }                                                                            \
        _Pragma("unroll")                                                            \
        for (int l = 0; l < 4; l++) {            /* B: 64 k-rows x 16 n-chunks */    \
            int a = tid + 256 * l;                                                   \
            int row = a >> 4, ch = a & 15;                                           \
            cpa16(Bs + (st) * O_STG + row * GO_LD + ch * 8,                          \
                  g_wob + (size_t)((k0) + row) * EDIM + n0 + ch * 8);                \
        }                                                                            \
        CP_COMMIT();                                                                 \
    }

    GO_LOAD(0, 0);
    const int NT = D1 / 64;                      // 12
    for (int t = 0; t < NT; t++) {
        if (t + 1 < NT) { GO_LOAD((t + 1) * 64, (t + 1) & 1); CP_WAIT1(); }
        else           { CP_WAIT0(); }
        __syncthreads();
        const __nv_bfloat16* Ac = As + (t & 1) * O_STG;
        const __nv_bfloat16* Bc = Bs + (t & 1) * O_STG;
#pragma unroll
        for (int kk = 0; kk < 64; kk += 16) {
            wmma::fragment<wmma::matrix_a, 16, 16, 16, __nv_bfloat16, wmma::col_major> af[2];
            wmma::fragment<wmma::matrix_b, 16, 16, 16, __nv_bfloat16, wmma::row_major> bf[4];
#pragma unroll
            for (int i = 0; i < 2; i++)
                wmma::load_matrix_sync(af[i], Ac + kk * GO_LD + wm * 32 + 16 * i, GO_LD);
#pragma unroll
            for (int j = 0; j < 4; j++)
                wmma::load_matrix_sync(bf[j], Bc + kk * GO_LD + wn * 64 + 16 * j, GO_LD);
#pragma unroll
            for (int i = 0; i < 2; i++)
#pragma unroll
                for (int j = 0; j < 4; j++) wmma::mma_sync(acc[i][j], af[i], bf[j], acc[i][j]);
        }
        __syncthreads();
    }
#pragma unroll
    for (int i = 0; i < 2; i++)
#pragma unroll
        for (int j = 0; j < 4; j++)
            wmma::store_matrix_sync(St + (wm * 32 + 16 * i) * GS_LD + wn * 64 + 16 * j,
                                    acc[i][j], GS_LD, wmma::mem_row_major);
    __syncthreads();
#pragma unroll 4
    for (int l = 0; l < 64; l++) {
        int a = tid + 256 * l;
        int i = a >> 7, j = a & 127;             // j contiguous -> coalesced out/x
        size_t go = (size_t)(m0 + i) * EDIM + n0 + j;
        out[go] = St[i * GS_LD + j] + bo[n0 + j] + x[go];
    }
#undef GO_LOAD
}

// ---------------- launch ------------------------------------------------------
extern "C" void kernel_launch(void* const* d_in, const int* in_sizes, int n_in,
                              void* d_out, int out_size) {
    (void)in_sizes; (void)n_in; (void)out_size;
    const float* x     = (const float*)d_in[0];
    const float* Wu    = (const float*)d_in[3];
    const float* bu    = (const float*)d_in[4];
    const float* Wv    = (const float*)d_in[5];
    const float* bv    = (const float*)d_in[6];
    const float* Wo    = (const float*)d_in[7];
    const float* bo    = (const float*)d_in[8];
    const float* r1_pw = (const float*)d_in[9];
    const float* r1_pb = (const float*)d_in[10];
    const float* r1_lw = (const float*)d_in[11];
    const float* r1_lb = (const float*)d_in[12];
    const float* r1_ow = (const float*)d_in[13];
    const float* r1_ob = (const float*)d_in[14];
    const float* r2_pw = (const float*)d_in[15];
    const float* r2_pb = (const float*)d_in[16];
    const float* r2_lw = (const float*)d_in[17];
    const float* r2_lb = (const float*)d_in[18];
    const float* r2_ow = (const float*)d_in[19];
    const float* r2_ob = (const float*)d_in[20];
    float* out = (float*)d_out;

    cudaFuncSetAttribute(gemm_uv_kernel,  cudaFuncAttributeMaxDynamicSharedMemorySize, GEMM_SMEM);
    cudaFuncSetAttribute(gemm_out_kernel, cudaFuncAttributeMaxDynamicSharedMemorySize, GOUT_SMEM);
    cudaFuncSetAttribute(conv_kernel,     cudaFuncAttributeMaxDynamicSharedMemorySize, CONV_SMEM);

    cvt_kernel <<<1152, 256>>>(Wu, Wv, Wo);
    norm_kernel<<<4096, 256>>>(x);
    gemm_uv_kernel<<<dim3(TOK / 128, D1 / 128, 2), 256, GEMM_SMEM>>>(bu, bv);

    rpe_l0<<<512, 256>>>(r1_pw, r1_pb, r2_pw, r2_pb);                       // -> g_rA
    rpe_hidden<<<dim3(8, 8, 2), 256>>>(r1_lw, r1_lb, r2_lw, r2_lb, 0, 0);   // rA -> rB
    rpe_hidden<<<dim3(8, 8, 2), 256>>>(r1_lw, r1_lb, r2_lw, r2_lb, 1, 1);   // rB -> rA
    rpe_hidden<<<dim3(8, 8, 2), 256>>>(r1_lw, r1_lb, r2_lw, r2_lb, 2, 0);   // rA -> rB
    rpe_final <<<dim3(12, 8, 2), 256>>>(r1_ow, r1_ob, r2_ow, r2_ob);        // rB -> a_tabs
    toep_kernel<<<D1, 256>>>();

    conv_kernel<<<dim3(D1 / 2, BSZ), 256, CONV_SMEM>>>();
    gemm_out_kernel<<<dim3(TOK / 128, EDIM / 128), 256, GOUT_SMEM>>>(x, bo, out);
}